// round 7
// baseline (speedup 1.0000x reference)
#include <cuda_runtime.h>

// Critic_66511863546286 — folded attention critic, round 7.
// B=256, S=1024, H=256, feat dims = 2, 3 iterations.
// R7: load balance. 1024 CTAs (4 S-chunks of 256 per batch) x 128 threads,
// inner loop identical to R6 (h-pair f32x2 + 2 pts/thread). Per-batch
// softmax combined across the 4 chunks in-kernel via global-memory partials
// + atomic counter + spin (all 1024 CTAs provably co-resident:
// __launch_bounds__(128,8) -> 8 CTAs/SM -> 1184 slots).

#define NB 256
#define NS 1024
#define NH 256
#define NHP 128   // h-pairs
#define K3 768
#define NITER 3
#define NFC 20
#define CHUNKS 4
#define CPTS 256  // points per chunk
#define BT 128    // threads per CTA; thread t owns points t and t+128 of chunk

// Precomputed fused coefficients (natural scale).
__device__ float4 gABp[NH];  // (A0, A1, B0, B1) per h
__device__ float4 gCdv[NH];  // (C0, C1, d, v[h])
__device__ float2 gF[NFC];   // fc1_w · sw
__device__ float  gfb[NFC];  // fc1_w · sb + fc1_b

// Cross-chunk combine scratch (indexed by it*NB+b). scrC is memset to 0
// before every attn launch (graph-capturable cudaMemsetAsync).
__device__ float4 scrP[NITER * NB * CHUNKS];  // (m, sumP, sumPx0, sumPx1)
__device__ int    scrC[NITER * NB];
__device__ float2 scrZ[NITER * NB];

__device__ __forceinline__ float ex2_approx(float x) {
    float y; asm("ex2.approx.f32 %0, %1;" : "=f"(y) : "f"(x)); return y;
}
__device__ __forceinline__ float tanh_approx(float x) {
    float y; asm("tanh.approx.f32 %0, %1;" : "=f"(y) : "f"(x)); return y;
}
__device__ __forceinline__ unsigned long long pack2(float lo, float hi) {
    unsigned long long r;
    asm("mov.b64 %0, {%1, %2};" : "=l"(r) : "f"(lo), "f"(hi));
    return r;
}
__device__ __forceinline__ unsigned long long fma2(
    unsigned long long a, unsigned long long b, unsigned long long c) {
    unsigned long long r;
    asm("fma.rn.f32x2 %0, %1, %2, %3;" : "=l"(r) : "l"(a), "l"(b), "l"(c));
    return r;
}
__device__ __forceinline__ void unpack2(unsigned long long p, float& lo, float& hi) {
    asm("mov.b64 {%0, %1}, %2;" : "=f"(lo), "=f"(hi) : "l"(p));
}

// ---------------------------------------------------------------------------
// Precompute: fold W through the 1x1-conv encoders.
// ---------------------------------------------------------------------------
__global__ void precompute_kernel(
    const float* __restrict__ sw, const float* __restrict__ sb,
    const float* __restrict__ dw, const float* __restrict__ db,
    const float* __restrict__ W,  const float* __restrict__ v,
    const float* __restrict__ fc1_w, const float* __restrict__ fc1_b)
{
    __shared__ float sred[8][8];
    int tid = threadIdx.x;
    int blk = blockIdx.x;
    int lane = tid & 31, w = tid >> 5;

    if (blk < NH) {
        int h = blk;
        float ws = W[h * K3 + tid];
        float wd = W[h * K3 + 256 + tid];
        float wc = W[h * K3 + 512 + tid];
        float s0 = sw[tid * 2 + 0], s1 = sw[tid * 2 + 1];
        float sbk = sb[tid];
        float p[7];
        p[0] = ws * s0;
        p[1] = ws * s1;
        p[2] = wd * dw[tid * 2 + 0];
        p[3] = wd * dw[tid * 2 + 1];
        p[4] = wc * s0;
        p[5] = wc * s1;
        p[6] = ws * sbk + wd * db[tid] + wc * sbk;
        #pragma unroll
        for (int o = 16; o > 0; o >>= 1)
            #pragma unroll
            for (int i = 0; i < 7; i++)
                p[i] += __shfl_xor_sync(0xffffffffu, p[i], o);
        if (lane == 0) {
            #pragma unroll
            for (int i = 0; i < 7; i++) sred[w][i] = p[i];
        }
        __syncthreads();
        if (tid == 0) {
            float q[7];
            #pragma unroll
            for (int i = 0; i < 7; i++) {
                q[i] = 0.f;
                for (int ww = 0; ww < 8; ww++) q[i] += sred[ww][i];
            }
            gABp[h] = make_float4(q[0], q[1], q[2], q[3]);
            gCdv[h] = make_float4(q[4], q[5], q[6], v[h]);
        }
    } else {
        int j = blk - NH;
        float fw = fc1_w[j * NH + tid];
        float p0 = fw * sw[tid * 2 + 0];
        float p1 = fw * sw[tid * 2 + 1];
        float p2 = fw * sb[tid];
        #pragma unroll
        for (int o = 16; o > 0; o >>= 1) {
            p0 += __shfl_xor_sync(0xffffffffu, p0, o);
            p1 += __shfl_xor_sync(0xffffffffu, p1, o);
            p2 += __shfl_xor_sync(0xffffffffu, p2, o);
        }
        if (lane == 0) { sred[w][0] = p0; sred[w][1] = p1; sred[w][2] = p2; }
        __syncthreads();
        if (tid == 0) {
            float q0 = 0.f, q1 = 0.f, q2 = 0.f;
            for (int ww = 0; ww < 8; ww++) {
                q0 += sred[ww][0]; q1 += sred[ww][1]; q2 += sred[ww][2];
            }
            gF[j] = make_float2(q0, q1);
            gfb[j] = q2 + fc1_b[j];
        }
    }
}

// ---------------------------------------------------------------------------
// Main kernel: 1024 CTAs, CTA = (batch b, chunk c) covering 256 points.
// 128 threads; thread t owns chunk points t (lo) and t+128 (hi).
// ---------------------------------------------------------------------------
__global__ void __launch_bounds__(BT, 8)
attn_kernel(const float* __restrict__ stat, const float* __restrict__ dyn,
            const float* __restrict__ istate,
            const float* __restrict__ fc2_w, const float* __restrict__ fc2_b,
            float* __restrict__ out)
{
    __shared__ ulonglong2 sAB[NHP];   // {(A0h,A0h1), (A1h,A1h1)}
    __shared__ ulonglong2 sBB[NHP];   // {(B0h,B0h1), (B1h,B1h1)}
    __shared__ ulonglong2 sGV[NHP];   // {(gh,gh1),  (vh,vh1)}
    __shared__ float4 sCdv[NH];       // (C0,C1,d,v)
    __shared__ float sredM[4], sredP[4], sredX[4], sredY[4];
    __shared__ float bc[1];
    __shared__ float2 zsh;

    const float LOG2E = 1.4426950408889634f;
    int bid = blockIdx.x;
    int b = bid >> 2;                 // batch
    int c = bid & 3;                  // chunk
    int t = threadIdx.x;              // 0..127
    int lane = t & 31, warp = t >> 5;

    const float* sbase = stat + b * 2 * NS;
    const float* dbase = dyn  + b * 2 * NS;
    int sl = c * CPTS + t;            // point lo
    // features for points sl and sl+128, duplicated into f32x2
    float x0l = sbase[sl],        x0h = sbase[sl + 128];
    float x1l = sbase[NS + sl],   x1h = sbase[NS + sl + 128];
    float y0l = dbase[sl],        y0h = dbase[sl + 128];
    float y1l = dbase[NS + sl],   y1h = dbase[NS + sl + 128];
    unsigned long long x0lp = pack2(x0l, x0l), x0hp = pack2(x0h, x0h);
    unsigned long long x1lp = pack2(x1l, x1l), x1hp = pack2(x1h, x1h);
    unsigned long long y0lp = pack2(y0l, y0l), y0hp = pack2(y0h, y0h);
    unsigned long long y1lp = pack2(y1l, y1l), y1hp = pack2(y1h, y1h);

    // coefficient staging
    sCdv[t] = gCdv[t];
    sCdv[t + 128] = gCdv[t + 128];
    {
        float4 pa = gABp[2 * t];
        float4 pb = gABp[2 * t + 1];
        sAB[t] = make_ulonglong2(pack2(pa.x, pb.x), pack2(pa.y, pb.y));
        sBB[t] = make_ulonglong2(pack2(pa.z, pb.z), pack2(pa.w, pb.w));
    }

    float z0 = istate[b * 2 + 0];
    float z1 = istate[b * 2 + 1];

    for (int it = 0; it < NITER; it++) {
        __syncthreads();
        {   // one h-pair per thread (NHP == BT)
            float4 ca = sCdv[2 * t];
            float4 cb = sCdv[2 * t + 1];
            float ga = fmaf(ca.x, z0, fmaf(ca.y, z1, ca.z));
            float gb = fmaf(cb.x, z0, fmaf(cb.y, z1, cb.z));
            sGV[t] = make_ulonglong2(pack2(ga, gb), pack2(ca.w, cb.w));
        }
        __syncthreads();

        // scores: t = sum over h-pairs of (v,v') * tanh(A·x + B·y + (g,g'))
        unsigned long long accl = 0ull, acch = 0ull;
        #pragma unroll 4
        for (int k = 0; k < NHP; k++) {
            ulonglong2 a2 = sAB[k];
            ulonglong2 b2 = sBB[k];
            ulonglong2 gv = sGV[k];

            unsigned long long argl = fma2(a2.x, x0lp, gv.x);
            argl = fma2(a2.y, x1lp, argl);
            argl = fma2(b2.x, y0lp, argl);
            argl = fma2(b2.y, y1lp, argl);

            unsigned long long argh = fma2(a2.x, x0hp, gv.x);
            argh = fma2(a2.y, x1hp, argh);
            argh = fma2(b2.x, y0hp, argh);
            argh = fma2(b2.y, y1hp, argh);

            float l0, l1, h0, h1;
            unpack2(argl, l0, l1);
            unpack2(argh, h0, h1);
            accl = fma2(gv.y, pack2(tanh_approx(l0), tanh_approx(l1)), accl);
            acch = fma2(gv.y, pack2(tanh_approx(h0), tanh_approx(h1)), acch);
        }
        float ta, tb, tc, td;
        unpack2(accl, ta, tb);
        unpack2(acch, tc, td);
        float t0 = ta + tb;   // score of point sl
        float t1 = tc + td;   // score of point sl+128

        // chunk-local max
        float m = fmaxf(t0, t1);
        #pragma unroll
        for (int o = 16; o > 0; o >>= 1)
            m = fmaxf(m, __shfl_xor_sync(0xffffffffu, m, o));
        if (lane == 0) sredM[warp] = m;
        __syncthreads();
        if (t == 0) {
            bc[0] = fmaxf(fmaxf(sredM[0], sredM[1]), fmaxf(sredM[2], sredM[3]));
        }
        __syncthreads();
        float M = bc[0];

        // chunk-local softmax partials
        float p0 = ex2_approx((t0 - M) * LOG2E);
        float p1 = ex2_approx((t1 - M) * LOG2E);
        float a  = p0 + p1;
        float bx = fmaf(p0, x0l, p1 * x0h);
        float by = fmaf(p0, x1l, p1 * x1h);
        #pragma unroll
        for (int o = 16; o > 0; o >>= 1) {
            a  += __shfl_xor_sync(0xffffffffu, a,  o);
            bx += __shfl_xor_sync(0xffffffffu, bx, o);
            by += __shfl_xor_sync(0xffffffffu, by, o);
        }
        if (lane == 0) { sredP[warp] = a; sredX[warp] = bx; sredY[warp] = by; }
        __syncthreads();

        if (t == 0) {
            float S = sredP[0] + sredP[1] + sredP[2] + sredP[3];
            float X = sredX[0] + sredX[1] + sredX[2] + sredX[3];
            float Y = sredY[0] + sredY[1] + sredY[2] + sredY[3];
            int idx = it * NB + b;
            scrP[idx * CHUNKS + c] = make_float4(M, S, X, Y);
            __threadfence();
            int old = atomicAdd(&scrC[idx], 1);
            if (old == CHUNKS - 1) {
                // combiner: all partials visible
                __threadfence();
                float4 q0 = scrP[idx * CHUNKS + 0];
                float4 q1 = scrP[idx * CHUNKS + 1];
                float4 q2 = scrP[idx * CHUNKS + 2];
                float4 q3 = scrP[idx * CHUNKS + 3];
                float GM = fmaxf(fmaxf(q0.x, q1.x), fmaxf(q2.x, q3.x));
                float w0 = ex2_approx((q0.x - GM) * LOG2E);
                float w1 = ex2_approx((q1.x - GM) * LOG2E);
                float w2 = ex2_approx((q2.x - GM) * LOG2E);
                float w3 = ex2_approx((q3.x - GM) * LOG2E);
                float Z  = w0 * q0.y + w1 * q1.y + w2 * q2.y + w3 * q3.y;
                float Xc = w0 * q0.z + w1 * q1.z + w2 * q2.z + w3 * q3.z;
                float Yc = w0 * q0.w + w1 * q1.w + w2 * q2.w + w3 * q3.w;
                float inv = 1.f / Z;
                float z0n = Xc * inv, z1n = Yc * inv;
                if (it == NITER - 1) {
                    // output MLP (folded through sw)
                    float o = fc2_b[0];
                    #pragma unroll
                    for (int j = 0; j < NFC; j++) {
                        float hv = fmaf(gF[j].x, z0n, fmaf(gF[j].y, z1n, gfb[j]));
                        hv = fmaxf(hv, 0.f);
                        o = fmaf(fc2_w[j], hv, o);
                    }
                    out[b] = o;
                } else {
                    scrZ[idx] = make_float2(z0n, z1n);
                    __threadfence();
                    atomicAdd(&scrC[idx], CHUNKS);   // release: cnt -> 8
                }
                zsh = make_float2(z0n, z1n);
            } else if (it < NITER - 1) {
                // spin until combiner releases z for this (it, b)
                while (atomicAdd(&scrC[idx], 0) < 2 * CHUNKS) __nanosleep(64);
                __threadfence();
                zsh = scrZ[idx];
            }
        }
        __syncthreads();
        z0 = zsh.x;    // stale/unused on last iteration for non-combiners
        z1 = zsh.y;
    }
}

extern "C" void kernel_launch(void* const* d_in, const int* in_sizes, int n_in,
                              void* d_out, int out_size)
{
    const float* stat   = (const float*)d_in[0];   // [256, 2, 1024]
    const float* dyn    = (const float*)d_in[1];   // [256, 2, 1024]
    const float* istate = (const float*)d_in[2];   // [256, 2]
    const float* sw     = (const float*)d_in[3];   // [256, 2]
    const float* sb     = (const float*)d_in[4];   // [256]
    const float* dw     = (const float*)d_in[5];   // [256, 2]
    const float* db     = (const float*)d_in[6];   // [256]
    const float* v      = (const float*)d_in[7];   // [1, 256]
    const float* W      = (const float*)d_in[8];   // [256, 768]
    const float* fc1_w  = (const float*)d_in[9];   // [20, 256]
    const float* fc1_b  = (const float*)d_in[10];  // [20]
    const float* fc2_w  = (const float*)d_in[11];  // [1, 20]
    const float* fc2_b  = (const float*)d_in[12];  // [1]
    float* out = (float*)d_out;                    // [256, 1]

    // zero the arrival counters for this launch (graph-capturable)
    void* cptr = 0;
    cudaGetSymbolAddress(&cptr, scrC);
    cudaMemsetAsync(cptr, 0, sizeof(int) * NITER * NB);

    precompute_kernel<<<NH + NFC, 256>>>(sw, sb, dw, db, W, v, fc1_w, fc1_b);
    attn_kernel<<<NB * CHUNKS, BT>>>(stat, dyn, istate, fc2_w, fc2_b, out);
}

// round 8
// speedup vs baseline: 1.1356x; 1.1356x over previous
#include <cuda_runtime.h>
#include <cuda_fp16.h>

// Critic_66511863546286 — folded attention critic, round 8.
// B=256, S=1024, H=256, feat dims = 2, 3 iterations.
// R8 = R6 structure (256 CTAs x 512 thr, 2 pts/thread, h-pairs) with the
// entire inner chain in packed f16x2: HFMA2 affine, tanh.approx.f16x2
// (1 MUFU per 2 tanh -> MUFU halved), all 4 coefficient half2 pairs in ONE
// LDS.128 + (g,v) in one LDS.64 (LDS bytes ~halved). Scores accumulated in
// f16x2 over 16-h-pair chunks, flushed to f32. New binder: FMA pipe.

#define NB 256
#define NS 1024
#define NH 256
#define NHP 128   // h-pairs
#define K3 768
#define NITER 3
#define NFC 20
#define BT 512    // thread t owns points t (lo) and t+512 (hi)

// Precomputed fused coefficients (natural scale, f32 masters).
__device__ float4 gABp[NH];  // (A0, A1, B0, B1) per h
__device__ float4 gCdv[NH];  // (C0, C1, d, v[h])
__device__ float2 gF[NFC];   // fc1_w · sw
__device__ float  gfb[NFC];  // fc1_w · sb + fc1_b

__device__ __forceinline__ float ex2_approx(float x) {
    float y; asm("ex2.approx.f32 %0, %1;" : "=f"(y) : "f"(x)); return y;
}
__device__ __forceinline__ unsigned hfma2u(unsigned a, unsigned b, unsigned c) {
    unsigned d;
    asm("fma.rn.f16x2 %0, %1, %2, %3;" : "=r"(d) : "r"(a), "r"(b), "r"(c));
    return d;
}
__device__ __forceinline__ unsigned tanh16x2(unsigned x) {
    unsigned y; asm("tanh.approx.f16x2 %0, %1;" : "=r"(y) : "r"(x)); return y;
}
__device__ __forceinline__ unsigned f2h2(float a, float b) {
    __half2 h = __floats2half2_rn(a, b);
    return *reinterpret_cast<unsigned*>(&h);
}
__device__ __forceinline__ float h2sum(unsigned u) {
    __half2 h = *reinterpret_cast<__half2*>(&u);
    float2 f = __half22float2(h);
    return f.x + f.y;
}

// ---------------------------------------------------------------------------
// Precompute: fold W through the 1x1-conv encoders (f32 masters).
// ---------------------------------------------------------------------------
__global__ void precompute_kernel(
    const float* __restrict__ sw, const float* __restrict__ sb,
    const float* __restrict__ dw, const float* __restrict__ db,
    const float* __restrict__ W,  const float* __restrict__ v,
    const float* __restrict__ fc1_w, const float* __restrict__ fc1_b)
{
    __shared__ float sred[8][8];
    int tid = threadIdx.x;
    int blk = blockIdx.x;
    int lane = tid & 31, w = tid >> 5;

    if (blk < NH) {
        int h = blk;
        float ws = W[h * K3 + tid];
        float wd = W[h * K3 + 256 + tid];
        float wc = W[h * K3 + 512 + tid];
        float s0 = sw[tid * 2 + 0], s1 = sw[tid * 2 + 1];
        float sbk = sb[tid];
        float p[7];
        p[0] = ws * s0;
        p[1] = ws * s1;
        p[2] = wd * dw[tid * 2 + 0];
        p[3] = wd * dw[tid * 2 + 1];
        p[4] = wc * s0;
        p[5] = wc * s1;
        p[6] = ws * sbk + wd * db[tid] + wc * sbk;
        #pragma unroll
        for (int o = 16; o > 0; o >>= 1)
            #pragma unroll
            for (int i = 0; i < 7; i++)
                p[i] += __shfl_xor_sync(0xffffffffu, p[i], o);
        if (lane == 0) {
            #pragma unroll
            for (int i = 0; i < 7; i++) sred[w][i] = p[i];
        }
        __syncthreads();
        if (tid == 0) {
            float q[7];
            #pragma unroll
            for (int i = 0; i < 7; i++) {
                q[i] = 0.f;
                for (int ww = 0; ww < 8; ww++) q[i] += sred[ww][i];
            }
            gABp[h] = make_float4(q[0], q[1], q[2], q[3]);
            gCdv[h] = make_float4(q[4], q[5], q[6], v[h]);
        }
    } else {
        int j = blk - NH;
        float fw = fc1_w[j * NH + tid];
        float p0 = fw * sw[tid * 2 + 0];
        float p1 = fw * sw[tid * 2 + 1];
        float p2 = fw * sb[tid];
        #pragma unroll
        for (int o = 16; o > 0; o >>= 1) {
            p0 += __shfl_xor_sync(0xffffffffu, p0, o);
            p1 += __shfl_xor_sync(0xffffffffu, p1, o);
            p2 += __shfl_xor_sync(0xffffffffu, p2, o);
        }
        if (lane == 0) { sred[w][0] = p0; sred[w][1] = p1; sred[w][2] = p2; }
        __syncthreads();
        if (tid == 0) {
            float q0 = 0.f, q1 = 0.f, q2 = 0.f;
            for (int ww = 0; ww < 8; ww++) {
                q0 += sred[ww][0]; q1 += sred[ww][1]; q2 += sred[ww][2];
            }
            gF[j] = make_float2(q0, q1);
            gfb[j] = q2 + fc1_b[j];
        }
    }
}

// ---------------------------------------------------------------------------
// Main kernel: one block per batch; 512 threads; thread t owns points
// t (lo) and t+512 (hi); h in f16x2 pairs, full half2 inner chain.
// ---------------------------------------------------------------------------
__global__ void __launch_bounds__(BT, 2)
attn_kernel(const float* __restrict__ stat, const float* __restrict__ dyn,
            const float* __restrict__ istate,
            const float* __restrict__ fc2_w, const float* __restrict__ fc2_b,
            float* __restrict__ out)
{
    __shared__ uint4 sC[NHP];        // (A0pair, A1pair, B0pair, B1pair) half2s
    __shared__ uint2 sGV[NHP];       // (g-pair, v-pair) half2s, g rewritten/iter
    __shared__ float4 sCdv[NH];      // (C0,C1,d,v) f32
    __shared__ float sredM[16], sredP[16], sredX[16], sredY[16];
    __shared__ float bc[4];

    const float LOG2E = 1.4426950408889634f;
    int b = blockIdx.x;
    int s = threadIdx.x;              // 0..511
    int lane = s & 31, warp = s >> 5;

    // features for points s (lo) and s+512 (hi)
    float x0l = stat[b * 2 * NS + s],      x0h = stat[b * 2 * NS + s + BT];
    float x1l = stat[b * 2 * NS + NS + s], x1h = stat[b * 2 * NS + NS + s + BT];
    float y0l = dyn[b * 2 * NS + s],       y0h = dyn[b * 2 * NS + s + BT];
    float y1l = dyn[b * 2 * NS + NS + s],  y1h = dyn[b * 2 * NS + NS + s + BT];
    // duplicated half2 versions for the packed inner loop
    unsigned x0l2 = f2h2(x0l, x0l), x0h2 = f2h2(x0h, x0h);
    unsigned x1l2 = f2h2(x1l, x1l), x1h2 = f2h2(x1h, x1h);
    unsigned y0l2 = f2h2(y0l, y0l), y0h2 = f2h2(y0h, y0h);
    unsigned y1l2 = f2h2(y1l, y1l), y1h2 = f2h2(y1h, y1h);

    if (s < NH) sCdv[s] = gCdv[s];
    if (s < NHP) {
        float4 pa = gABp[2 * s];
        float4 pb = gABp[2 * s + 1];
        sC[s] = make_uint4(f2h2(pa.x, pb.x), f2h2(pa.y, pb.y),
                           f2h2(pa.z, pb.z), f2h2(pa.w, pb.w));
    }

    float z0 = istate[b * 2 + 0];
    float z1 = istate[b * 2 + 1];

    for (int it = 0; it < NITER; it++) {
        __syncthreads();
        if (s < NHP) {
            float4 ca = sCdv[2 * s];
            float4 cb = sCdv[2 * s + 1];
            float ga = fmaf(ca.x, z0, fmaf(ca.y, z1, ca.z));
            float gb = fmaf(cb.x, z0, fmaf(cb.y, z1, cb.z));
            sGV[s] = make_uint2(f2h2(ga, gb), f2h2(ca.w, cb.w));
        }
        __syncthreads();

        // scores: per point, t = sum over h-pairs of (v,v')*tanh(A·x+B·y+(g,g'))
        // f16x2 accumulate over 16-h-pair chunks, flushed to f32.
        float t0 = 0.f, t1 = 0.f;
        #pragma unroll
        for (int kc = 0; kc < NHP / 16; kc++) {
            unsigned accl = 0u, acch = 0u;   // half2 (0,0)
            #pragma unroll
            for (int j = 0; j < 16; j++) {
                int k = kc * 16 + j;
                uint4 cc = sC[k];            // LDS.128
                uint2 gv = sGV[k];           // LDS.64

                unsigned argl = hfma2u(cc.x, x0l2, gv.x);
                argl = hfma2u(cc.y, x1l2, argl);
                argl = hfma2u(cc.z, y0l2, argl);
                argl = hfma2u(cc.w, y1l2, argl);

                unsigned argh = hfma2u(cc.x, x0h2, gv.x);
                argh = hfma2u(cc.y, x1h2, argh);
                argh = hfma2u(cc.z, y0h2, argh);
                argh = hfma2u(cc.w, y1h2, argh);

                accl = hfma2u(gv.y, tanh16x2(argl), accl);
                acch = hfma2u(gv.y, tanh16x2(argh), acch);
            }
            t0 += h2sum(accl);
            t1 += h2sum(acch);
        }

        // block max over all 1024 points
        float m = fmaxf(t0, t1);
        #pragma unroll
        for (int o = 16; o > 0; o >>= 1)
            m = fmaxf(m, __shfl_xor_sync(0xffffffffu, m, o));
        if (lane == 0) sredM[warp] = m;
        __syncthreads();
        if (s < 16) {
            float mm = sredM[s];
            #pragma unroll
            for (int o = 8; o > 0; o >>= 1)
                mm = fmaxf(mm, __shfl_xor_sync(0xffffu, mm, o));
            if (s == 0) bc[0] = mm;
        }
        __syncthreads();
        float M = bc[0];

        // softmax weights + weighted feature sums (all f32)
        float p0 = ex2_approx((t0 - M) * LOG2E);
        float p1 = ex2_approx((t1 - M) * LOG2E);
        float a  = p0 + p1;
        float bx = fmaf(p0, x0l, p1 * x0h);
        float by = fmaf(p0, x1l, p1 * x1h);
        #pragma unroll
        for (int o = 16; o > 0; o >>= 1) {
            a  += __shfl_xor_sync(0xffffffffu, a,  o);
            bx += __shfl_xor_sync(0xffffffffu, bx, o);
            by += __shfl_xor_sync(0xffffffffu, by, o);
        }
        if (lane == 0) { sredP[warp] = a; sredX[warp] = bx; sredY[warp] = by; }
        __syncthreads();
        if (s < 16) {
            float aa = sredP[s], xx = sredX[s], yy = sredY[s];
            #pragma unroll
            for (int o = 8; o > 0; o >>= 1) {
                aa += __shfl_xor_sync(0xffffu, aa, o);
                xx += __shfl_xor_sync(0xffffu, xx, o);
                yy += __shfl_xor_sync(0xffffu, yy, o);
            }
            if (s == 0) { bc[1] = aa; bc[2] = xx; bc[3] = yy; }
        }
        __syncthreads();
        float inv = 1.f / bc[1];
        z0 = bc[2] * inv;   // xbar0
        z1 = bc[3] * inv;   // xbar1
    }

    // Output MLP (folded through sw), f32
    if (s == 0) {
        float o = fc2_b[0];
        #pragma unroll
        for (int j = 0; j < NFC; j++) {
            float hv = fmaf(gF[j].x, z0, fmaf(gF[j].y, z1, gfb[j]));
            hv = fmaxf(hv, 0.f);
            o = fmaf(fc2_w[j], hv, o);
        }
        out[b] = o;
    }
}

extern "C" void kernel_launch(void* const* d_in, const int* in_sizes, int n_in,
                              void* d_out, int out_size)
{
    const float* stat   = (const float*)d_in[0];   // [256, 2, 1024]
    const float* dyn    = (const float*)d_in[1];   // [256, 2, 1024]
    const float* istate = (const float*)d_in[2];   // [256, 2]
    const float* sw     = (const float*)d_in[3];   // [256, 2]
    const float* sb     = (const float*)d_in[4];   // [256]
    const float* dw     = (const float*)d_in[5];   // [256, 2]
    const float* db     = (const float*)d_in[6];   // [256]
    const float* v      = (const float*)d_in[7];   // [1, 256]
    const float* W      = (const float*)d_in[8];   // [256, 768]
    const float* fc1_w  = (const float*)d_in[9];   // [20, 256]
    const float* fc1_b  = (const float*)d_in[10];  // [20]
    const float* fc2_w  = (const float*)d_in[11];  // [1, 20]
    const float* fc2_b  = (const float*)d_in[12];  // [1]
    float* out = (float*)d_out;                    // [256, 1]

    precompute_kernel<<<NH + NFC, 256>>>(sw, sb, dw, db, W, v, fc1_w, fc1_b);
    attn_kernel<<<NB, BT>>>(stat, dyn, istate, fc2_w, fc2_b, out);
}

// round 9
// speedup vs baseline: 1.2559x; 1.1059x over previous
#include <cuda_runtime.h>
#include <cuda_fp16.h>

// Critic_66511863546286 — folded attention critic, round 9.
// B=256, S=1024, H=256, feat dims = 2, 3 iterations.
// R9 = R8 + MUFU/FMA pipe balancing: tanh.approx.f16x2 is double-pumped
// (rt~16; R6 and R8 both measured at the ~98K-cycle MUFU wall), so 1 of
// every 4 h-pair iterations evaluates tanh via an odd-quintic polynomial
// on the FMA pipe (4 HFMA2-class ops, zero MUFU). Per 4-j group:
// MUFU 96 cyc == FMA 96 cyc — balanced; budget 98K -> 73.7K cycles.

#define NB 256
#define NS 1024
#define NH 256
#define NHP 128   // h-pairs
#define K3 768
#define NITER 3
#define NFC 20
#define BT 512    // thread t owns points t (lo) and t+512 (hi)

// Precomputed fused coefficients (natural scale, f32 masters).
__device__ float4 gABp[NH];  // (A0, A1, B0, B1) per h
__device__ float4 gCdv[NH];  // (C0, C1, d, v[h])
__device__ float2 gF[NFC];   // fc1_w · sw
__device__ float  gfb[NFC];  // fc1_w · sb + fc1_b

__device__ __forceinline__ float ex2_approx(float x) {
    float y; asm("ex2.approx.f32 %0, %1;" : "=f"(y) : "f"(x)); return y;
}
__device__ __forceinline__ unsigned hfma2u(unsigned a, unsigned b, unsigned c) {
    unsigned d;
    asm("fma.rn.f16x2 %0, %1, %2, %3;" : "=r"(d) : "r"(a), "r"(b), "r"(c));
    return d;
}
__device__ __forceinline__ unsigned hmul2u(unsigned a, unsigned b) {
    unsigned d;
    asm("mul.rn.f16x2 %0, %1, %2;" : "=r"(d) : "r"(a), "r"(b));
    return d;
}
__device__ __forceinline__ unsigned tanh16x2(unsigned x) {
    unsigned y; asm("tanh.approx.f16x2 %0, %1;" : "=r"(y) : "r"(x)); return y;
}
__device__ __forceinline__ unsigned f2h2(float a, float b) {
    __half2 h = __floats2half2_rn(a, b);
    return *reinterpret_cast<unsigned*>(&h);
}
__device__ __forceinline__ float h2sum(unsigned u) {
    __half2 h = *reinterpret_cast<__half2*>(&u);
    float2 f = __half22float2(h);
    return f.x + f.y;
}

// ---------------------------------------------------------------------------
// Precompute: fold W through the 1x1-conv encoders (f32 masters).
// ---------------------------------------------------------------------------
__global__ void precompute_kernel(
    const float* __restrict__ sw, const float* __restrict__ sb,
    const float* __restrict__ dw, const float* __restrict__ db,
    const float* __restrict__ W,  const float* __restrict__ v,
    const float* __restrict__ fc1_w, const float* __restrict__ fc1_b)
{
    __shared__ float sred[8][8];
    int tid = threadIdx.x;
    int blk = blockIdx.x;
    int lane = tid & 31, w = tid >> 5;

    if (blk < NH) {
        int h = blk;
        float ws = W[h * K3 + tid];
        float wd = W[h * K3 + 256 + tid];
        float wc = W[h * K3 + 512 + tid];
        float s0 = sw[tid * 2 + 0], s1 = sw[tid * 2 + 1];
        float sbk = sb[tid];
        float p[7];
        p[0] = ws * s0;
        p[1] = ws * s1;
        p[2] = wd * dw[tid * 2 + 0];
        p[3] = wd * dw[tid * 2 + 1];
        p[4] = wc * s0;
        p[5] = wc * s1;
        p[6] = ws * sbk + wd * db[tid] + wc * sbk;
        #pragma unroll
        for (int o = 16; o > 0; o >>= 1)
            #pragma unroll
            for (int i = 0; i < 7; i++)
                p[i] += __shfl_xor_sync(0xffffffffu, p[i], o);
        if (lane == 0) {
            #pragma unroll
            for (int i = 0; i < 7; i++) sred[w][i] = p[i];
        }
        __syncthreads();
        if (tid == 0) {
            float q[7];
            #pragma unroll
            for (int i = 0; i < 7; i++) {
                q[i] = 0.f;
                for (int ww = 0; ww < 8; ww++) q[i] += sred[ww][i];
            }
            gABp[h] = make_float4(q[0], q[1], q[2], q[3]);
            gCdv[h] = make_float4(q[4], q[5], q[6], v[h]);
        }
    } else {
        int j = blk - NH;
        float fw = fc1_w[j * NH + tid];
        float p0 = fw * sw[tid * 2 + 0];
        float p1 = fw * sw[tid * 2 + 1];
        float p2 = fw * sb[tid];
        #pragma unroll
        for (int o = 16; o > 0; o >>= 1) {
            p0 += __shfl_xor_sync(0xffffffffu, p0, o);
            p1 += __shfl_xor_sync(0xffffffffu, p1, o);
            p2 += __shfl_xor_sync(0xffffffffu, p2, o);
        }
        if (lane == 0) { sred[w][0] = p0; sred[w][1] = p1; sred[w][2] = p2; }
        __syncthreads();
        if (tid == 0) {
            float q0 = 0.f, q1 = 0.f, q2 = 0.f;
            for (int ww = 0; ww < 8; ww++) {
                q0 += sred[ww][0]; q1 += sred[ww][1]; q2 += sred[ww][2];
            }
            gF[j] = make_float2(q0, q1);
            gfb[j] = q2 + fc1_b[j];
        }
    }
}

// ---------------------------------------------------------------------------
// Main kernel: one block per batch; 512 threads; thread t owns points
// t (lo) and t+512 (hi); h in f16x2 pairs, full half2 inner chain.
// 3/4 of h-pair iterations: MUFU tanh; 1/4: FMA-pipe polynomial tanh.
// ---------------------------------------------------------------------------
__global__ void __launch_bounds__(BT, 2)
attn_kernel(const float* __restrict__ stat, const float* __restrict__ dyn,
            const float* __restrict__ istate,
            const float* __restrict__ fc2_w, const float* __restrict__ fc2_b,
            float* __restrict__ out)
{
    __shared__ uint4 sC[NHP];        // (A0pair, A1pair, B0pair, B1pair) half2s
    __shared__ uint2 sGV[NHP];       // (g-pair, v-pair) half2s, g rewritten/iter
    __shared__ float4 sCdv[NH];      // (C0,C1,d,v) f32
    __shared__ float sredM[16], sredP[16], sredX[16], sredY[16];
    __shared__ float bc[4];

    const float LOG2E = 1.4426950408889634f;
    int b = blockIdx.x;
    int s = threadIdx.x;              // 0..511
    int lane = s & 31, warp = s >> 5;

    // odd-quintic tanh coefficients: tanh(x) ~= x*(1 + x2*(PA + PB*x2))
    const unsigned PA2 = f2h2(-0.3248f, -0.3248f);
    const unsigned PB2 = f2h2(0.0864f, 0.0864f);
    const unsigned ONE2 = f2h2(1.0f, 1.0f);

    // features for points s (lo) and s+512 (hi)
    float x0l = stat[b * 2 * NS + s],      x0h = stat[b * 2 * NS + s + BT];
    float x1l = stat[b * 2 * NS + NS + s], x1h = stat[b * 2 * NS + NS + s + BT];
    float y0l = dyn[b * 2 * NS + s],       y0h = dyn[b * 2 * NS + s + BT];
    float y1l = dyn[b * 2 * NS + NS + s],  y1h = dyn[b * 2 * NS + NS + s + BT];
    // duplicated half2 versions for the packed inner loop
    unsigned x0l2 = f2h2(x0l, x0l), x0h2 = f2h2(x0h, x0h);
    unsigned x1l2 = f2h2(x1l, x1l), x1h2 = f2h2(x1h, x1h);
    unsigned y0l2 = f2h2(y0l, y0l), y0h2 = f2h2(y0h, y0h);
    unsigned y1l2 = f2h2(y1l, y1l), y1h2 = f2h2(y1h, y1h);

    if (s < NH) sCdv[s] = gCdv[s];
    if (s < NHP) {
        float4 pa = gABp[2 * s];
        float4 pb = gABp[2 * s + 1];
        sC[s] = make_uint4(f2h2(pa.x, pb.x), f2h2(pa.y, pb.y),
                           f2h2(pa.z, pb.z), f2h2(pa.w, pb.w));
    }

    float z0 = istate[b * 2 + 0];
    float z1 = istate[b * 2 + 1];

    for (int it = 0; it < NITER; it++) {
        __syncthreads();
        if (s < NHP) {
            float4 ca = sCdv[2 * s];
            float4 cb = sCdv[2 * s + 1];
            float ga = fmaf(ca.x, z0, fmaf(ca.y, z1, ca.z));
            float gb = fmaf(cb.x, z0, fmaf(cb.y, z1, cb.z));
            sGV[s] = make_uint2(f2h2(ga, gb), f2h2(ca.w, cb.w));
        }
        __syncthreads();

        // scores: per point, t = sum over h-pairs of (v,v')*tanh(A·x+B·y+(g,g'))
        // f16x2 accumulate over 16-h-pair chunks, flushed to f32.
        float t0 = 0.f, t1 = 0.f;
        #pragma unroll
        for (int kc = 0; kc < NHP / 16; kc++) {
            unsigned accl = 0u, acch = 0u;   // half2 (0,0)
            #pragma unroll
            for (int j = 0; j < 16; j++) {
                int k = kc * 16 + j;
                uint4 cc = sC[k];            // LDS.128
                uint2 gv = sGV[k];           // LDS.64

                unsigned argl = hfma2u(cc.x, x0l2, gv.x);
                argl = hfma2u(cc.y, x1l2, argl);
                argl = hfma2u(cc.z, y0l2, argl);
                argl = hfma2u(cc.w, y1l2, argl);

                unsigned argh = hfma2u(cc.x, x0h2, gv.x);
                argh = hfma2u(cc.y, x1h2, argh);
                argh = hfma2u(cc.z, y0h2, argh);
                argh = hfma2u(cc.w, y1h2, argh);

                unsigned thl, thh;
                if ((j & 3) == 3) {
                    // FMA-pipe polynomial tanh (both packed pairs)
                    unsigned x2l = hmul2u(argl, argl);
                    unsigned ul = hfma2u(x2l, PB2, PA2);
                    unsigned wl = hfma2u(ul, x2l, ONE2);
                    thl = hmul2u(wl, argl);
                    unsigned x2h = hmul2u(argh, argh);
                    unsigned uh = hfma2u(x2h, PB2, PA2);
                    unsigned wh = hfma2u(uh, x2h, ONE2);
                    thh = hmul2u(wh, argh);
                } else {
                    thl = tanh16x2(argl);
                    thh = tanh16x2(argh);
                }
                accl = hfma2u(gv.y, thl, accl);
                acch = hfma2u(gv.y, thh, acch);
            }
            t0 += h2sum(accl);
            t1 += h2sum(acch);
        }

        // block max over all 1024 points
        float m = fmaxf(t0, t1);
        #pragma unroll
        for (int o = 16; o > 0; o >>= 1)
            m = fmaxf(m, __shfl_xor_sync(0xffffffffu, m, o));
        if (lane == 0) sredM[warp] = m;
        __syncthreads();
        if (s < 16) {
            float mm = sredM[s];
            #pragma unroll
            for (int o = 8; o > 0; o >>= 1)
                mm = fmaxf(mm, __shfl_xor_sync(0xffffu, mm, o));
            if (s == 0) bc[0] = mm;
        }
        __syncthreads();
        float M = bc[0];

        // softmax weights + weighted feature sums (all f32)
        float p0 = ex2_approx((t0 - M) * LOG2E);
        float p1 = ex2_approx((t1 - M) * LOG2E);
        float a  = p0 + p1;
        float bx = fmaf(p0, x0l, p1 * x0h);
        float by = fmaf(p0, x1l, p1 * x1h);
        #pragma unroll
        for (int o = 16; o > 0; o >>= 1) {
            a  += __shfl_xor_sync(0xffffffffu, a,  o);
            bx += __shfl_xor_sync(0xffffffffu, bx, o);
            by += __shfl_xor_sync(0xffffffffu, by, o);
        }
        if (lane == 0) { sredP[warp] = a; sredX[warp] = bx; sredY[warp] = by; }
        __syncthreads();
        if (s < 16) {
            float aa = sredP[s], xx = sredX[s], yy = sredY[s];
            #pragma unroll
            for (int o = 8; o > 0; o >>= 1) {
                aa += __shfl_xor_sync(0xffffu, aa, o);
                xx += __shfl_xor_sync(0xffffu, xx, o);
                yy += __shfl_xor_sync(0xffffu, yy, o);
            }
            if (s == 0) { bc[1] = aa; bc[2] = xx; bc[3] = yy; }
        }
        __syncthreads();
        float inv = 1.f / bc[1];
        z0 = bc[2] * inv;   // xbar0
        z1 = bc[3] * inv;   // xbar1
    }

    // Output MLP (folded through sw), f32
    if (s == 0) {
        float o = fc2_b[0];
        #pragma unroll
        for (int j = 0; j < NFC; j++) {
            float hv = fmaf(gF[j].x, z0, fmaf(gF[j].y, z1, gfb[j]));
            hv = fmaxf(hv, 0.f);
            o = fmaf(fc2_w[j], hv, o);
        }
        out[b] = o;
    }
}

extern "C" void kernel_launch(void* const* d_in, const int* in_sizes, int n_in,
                              void* d_out, int out_size)
{
    const float* stat   = (const float*)d_in[0];   // [256, 2, 1024]
    const float* dyn    = (const float*)d_in[1];   // [256, 2, 1024]
    const float* istate = (const float*)d_in[2];   // [256, 2]
    const float* sw     = (const float*)d_in[3];   // [256, 2]
    const float* sb     = (const float*)d_in[4];   // [256]
    const float* dw     = (const float*)d_in[5];   // [256, 2]
    const float* db     = (const float*)d_in[6];   // [256]
    const float* v      = (const float*)d_in[7];   // [1, 256]
    const float* W      = (const float*)d_in[8];   // [256, 768]
    const float* fc1_w  = (const float*)d_in[9];   // [20, 256]
    const float* fc1_b  = (const float*)d_in[10];  // [20]
    const float* fc2_w  = (const float*)d_in[11];  // [1, 20]
    const float* fc2_b  = (const float*)d_in[12];  // [1]
    float* out = (float*)d_out;                    // [256, 1]

    precompute_kernel<<<NH + NFC, 256>>>(sw, sb, dw, db, W, v, fc1_w, fc1_b);
    attn_kernel<<<NB, BT>>>(stat, dyn, istate, fc2_w, fc2_b, out);
}